// round 16
// baseline (speedup 1.0000x reference)
#include <cuda_runtime.h>

#define BS_    128
#define NF_    4
#define P_LO_  1024
#define P_HI_  16384
#define K_     9
#define NC_    36

// Allocation-free scratch.
__device__ int  g_cls_count[NC_];
__device__ int2 g_off[NC_][BS_];               // {b*NF*P_LO, b*NF*P_HI}
__device__ unsigned long long g_pack[P_HI_];   // per-point shuffle descriptor

// Merged prepass (same descriptor scheme as R13/R14):
//  CTAs 0..63 : pack shuffle descriptors; modes 0/1/2 as before.
//  CTAs 64..68: class offset lists, one warp per class (batch order kept).
__global__ void prepass_kernel(const int* __restrict__ cls_ids,
                               const int* __restrict__ nbr) {
    __shared__ int snb[8][288];
    const int cta  = blockIdx.x;
    const int tid  = threadIdx.x;
    const int lane = tid & 31;
    if (cta < 64) {
        const int wid = tid >> 5;
        const int W = cta * 8 + wid;
        const int h = W >> 3, t = W & 7;
        const int half = lane >> 4, j = lane & 15;
        const int row = 2 * h + half;
        const int p = row * 128 + 16 * t + j;

        const int4* s4 = reinterpret_cast<const int4*>(
            nbr + (size_t)(row * 128 + 16 * t) * K_);
        int4* d4 = reinterpret_cast<int4*>(snb[wid] + half * 144);
        d4[j]      = s4[j];
        d4[j + 16] = s4[j + 16];
        if (j < 4) d4[j + 32] = s4[j + 32];
        __syncwarp();
        const int* my = snb[wid] + half * 144 + j * 9;

        int r[K_], c[K_];
        int rmin = 32, cmin = 32, rmax = -1, cmax = -1;
        #pragma unroll
        for (int k = 0; k < K_; k++) {
            int v = my[k];
            r[k] = v >> 5; c[k] = v & 31;
            rmin = min(rmin, r[k]);  rmax = max(rmax, r[k]);
            cmin = min(cmin, c[k]);  cmax = max(cmax, c[k]);
        }
        #pragma unroll
        for (int o = 16; o; o >>= 1) {
            rmin = min(rmin, __shfl_xor_sync(0xffffffffu, rmin, o));
            rmax = max(rmax, __shfl_xor_sync(0xffffffffu, rmax, o));
            cmin = min(cmin, __shfl_xor_sync(0xffffffffu, cmin, o));
            cmax = max(cmax, __shfl_xor_sync(0xffffffffu, cmax, o));
        }
        const int rspan = rmax - rmin, cspan = cmax - cmin;
        int mode;
        if (rspan <= 3 && cspan <= 7)      mode = 0;
        else if (rspan <= 4 && cspan <= 5) mode = 1;
        else                               mode = 2;

        unsigned long long pk = ((unsigned long long)rmin << 45) |
                                ((unsigned long long)cmin << 50) |
                                ((unsigned long long)mode << 55);
        if (mode < 2) {
            #pragma unroll
            for (int k = 0; k < K_; k++) {
                int dr = r[k] - rmin, dc = c[k] - cmin;
                unsigned long long sl =
                    (unsigned long long)(mode == 0 ? dr * 8 + dc : dr * 6 + dc);
                pk |= sl << (5 * k);
            }
        }
        g_pack[p] = pk;
    } else {
        const int w = (cta - 64) * 8 + (tid >> 5);
        if (w < NC_) {
            int base = 0;
            #pragma unroll
            for (int chunk = 0; chunk < BS_ / 32; chunk++) {
                int i = chunk * 32 + lane;
                int v = cls_ids[i];
                unsigned m = __ballot_sync(0xffffffffu, v == w);
                if (v == w)
                    g_off[w][base + __popc(m & ((1u << lane) - 1))] =
                        make_int2(i * (NF_ * P_LO_), i * (NF_ * P_HI_));
                base += __popc(m);
            }
            if (lane == 0) g_cls_count[w] = base;
        }
    }
}

// Warp-autonomous main kernel. One CTA per (2-hi-row tile, class), looping
// over all 4 features: the f+1 weight strip (1152 B/warp, 3x LDG.128/lane)
// is prefetched into registers while f's sample loop runs -> deep MLP.
// Inner loop uses precomputed int offsets (no 64-bit IMAD chains).
__global__ void __launch_bounds__(256, 4)
upsample_kernel(const float* __restrict__ x,
                const int*   __restrict__ nbr,
                const float* __restrict__ wmap,
                const float* __restrict__ blo,
                const float* __restrict__ bhi,
                float*       __restrict__ out)
{
    __shared__ float sw[8][288];              // per-warp weight staging

    const int c = blockIdx.y;
    const int n = g_cls_count[c];
    if (n == 0) return;

    const int tid  = threadIdx.x;
    const int lane = tid & 31;
    const int wid  = tid >> 5;
    const int half = lane >> 4, j = lane & 15;
    const int row  = 2 * blockIdx.x + half;   // CTA covers hi rows {2bx, 2bx+1}
    const int p    = row * 128 + 16 * wid + j;

    const unsigned long long pk = g_pack[p];
    const int mode = (int)((pk >> 55) & 3);

    // f=0 weight prefetch (strip = this warp's 288 floats of wmap[c][0])
    const float4* wsrc = reinterpret_cast<const float4*>(
        wmap + (((size_t)c * NF_) * P_HI_ + (size_t)(row * 128 + 16 * wid)) * K_);
    const int WF4 = P_HI_ * K_ / 4;           // float4 stride between features
    float4 pf0 = wsrc[j], pf1 = wsrc[j + 16], pf2;
    if (j < 4) pf2 = wsrc[j + 32];

    // mode<2 shuffle state (warp-uniform mode)
    int sl[K_];
    int sidx = 0;
    if (mode < 2) {
        const int r0 = (int)((pk >> 45) & 31);
        const int c0 = (int)((pk >> 50) & 31);
        #pragma unroll
        for (int k = 0; k < K_; k++) sl[k] = (int)((pk >> (5 * k)) & 31);
        const int srow = min(r0 + (mode == 0 ? (lane >> 3) : lane / 6), 31);
        const int scol = min(c0 + (mode == 0 ? (lane & 7)  : lane % 6), 31);
        sidx = srow * 32 + scol;
    }

    const float* blo_c = blo + (size_t)c * NF_ * P_LO_;
    const float* bhi_c = bhi + (size_t)c * NF_ * P_HI_ + p;

    #pragma unroll
    for (int f = 0; f < NF_; f++) {
        // stage prefetched weights -> smem -> per-lane registers
        {
            float4* d4 = reinterpret_cast<float4*>(sw[wid] + half * 144);
            d4[j]      = pf0;
            d4[j + 16] = pf1;
            if (j < 4) d4[j + 32] = pf2;
        }
        __syncwarp();
        float wv[K_];
        {
            const float* my = sw[wid] + half * 144 + j * 9;
            #pragma unroll
            for (int k = 0; k < K_; k++) wv[k] = my[k];
        }
        __syncwarp();                          // all lanes read before next STS
        if (f + 1 < NF_) {                     // launch f+1's weight stream
            const float4* ws = wsrc + (size_t)(f + 1) * WF4;
            pf0 = ws[j]; pf1 = ws[j + 16];
            if (j < 4) pf2 = ws[j + 32];
        }

        const float bh    = bhi_c[(size_t)f * P_HI_];
        const float* x_f  = x   + (size_t)f * P_LO_;
        float*       o_f  = out + (size_t)f * P_HI_ + p;

        if (mode < 2) {
            const float blo_s  = blo_c[f * P_LO_ + sidx];
            const float* x_fs  = x_f + sidx;

            // rolling 2-deep sample prefetch
            int2  of0 = g_off[c][0];
            int2  of1 = (n > 1) ? g_off[c][1] : of0;
            float xv0 = x_fs[of0.x];
            float xv1 = x_fs[of1.x];

            for (int s = 0; s < n; s++) {
                const float y  = xv0 - blo_s;
                const int   oo = of0.y;
                of0 = of1; xv0 = xv1;
                if (s + 2 < n) {
                    of1 = g_off[c][s + 2];
                    xv1 = x_fs[of1.x];
                }
                float acc = bh;
                #pragma unroll
                for (int k = 0; k < K_; k++)
                    acc = fmaf(wv[k], __shfl_sync(0xffffffffu, y, sl[k]), acc);
                o_f[oo] = acc;
            }
        } else {
            // Safety net: direct global gather (cold; reload everything here).
            int nb[K_];
            float blo_nb[K_];
            #pragma unroll
            for (int k = 0; k < K_; k++) {
                nb[k]     = nbr[p * K_ + k];
                blo_nb[k] = blo_c[f * P_LO_ + nb[k]];
            }
            for (int s = 0; s < n; s++) {
                const int2 of = g_off[c][s];
                const float* xs = x_f + of.x;
                float acc = bh;
                #pragma unroll
                for (int k = 0; k < K_; k++)
                    acc = fmaf(wv[k], xs[nb[k]] - blo_nb[k], acc);
                o_f[of.y] = acc;
            }
        }
    }
}

extern "C" void kernel_launch(void* const* d_in, const int* in_sizes, int n_in,
                              void* d_out, int out_size) {
    const float* x    = (const float*)d_in[0];   // (BS, NF*P_LO) f32
    const int*   cls  = (const int*)  d_in[1];   // (BS,) i32
    const int*   nbr  = (const int*)  d_in[2];   // (P_HI, K) i32
    const float* wmap = (const float*)d_in[3];   // (NC, NF, P_HI, K) f32
    const float* blo  = (const float*)d_in[4];   // (NC, NF, P_LO) f32
    const float* bhi  = (const float*)d_in[5];   // (NC, NF, P_HI) f32
    float* out = (float*)d_out;                  // (BS, NF, P_HI) f32

    prepass_kernel<<<69, 256>>>(cls, nbr);
    dim3 grid(64, NC_);
    upsample_kernel<<<grid, 256>>>(x, nbr, wmap, blo, bhi, out);
}

// round 17
// speedup vs baseline: 1.4292x; 1.4292x over previous
#include <cuda_runtime.h>

#define BS_    128
#define NF_    4
#define P_LO_  1024
#define P_HI_  16384
#define K_     9
#define NC_    36

// Allocation-free scratch.
__device__ int      g_cls_count[NC_];
__device__ int2     g_off[NC_][BS_];            // {b*NF*P_LO, b*NF*P_HI}
__device__ unsigned g_wbase[512];               // per-warp {mode,r0,c0} (hot, 2KB)
__device__ unsigned long long g_pack[P_HI_];    // per-point shuffle lanes (5b x 9)

// Merged prepass.
//  CTAs 0..63 : descriptors. Warp W covers hi rows {2h,2h+1}, cols [16t,16t+16).
//               modes: 0: rspan<=3,cspan<=7 (slot=dr*8+dc); 1: rspan<=4,cspan<=5
//               (slot=dr*6+dc); 2: fallback. wbase = mode | r0<<2 | c0<<7.
//  CTAs 64..68: class offset lists, one warp per class (batch order kept).
__global__ void prepass_kernel(const int* __restrict__ cls_ids,
                               const int* __restrict__ nbr) {
    __shared__ int snb[8][288];
    const int cta  = blockIdx.x;
    const int tid  = threadIdx.x;
    const int lane = tid & 31;
    if (cta < 64) {
        const int wid = tid >> 5;
        const int W = cta * 8 + wid;
        const int h = W >> 3, t = W & 7;
        const int half = lane >> 4, j = lane & 15;
        const int row = 2 * h + half;
        const int p = row * 128 + 16 * t + j;

        // coalesced staging of this half-warp's 144 neighbor ints
        const int4* s4 = reinterpret_cast<const int4*>(
            nbr + (size_t)(row * 128 + 16 * t) * K_);
        int4* d4 = reinterpret_cast<int4*>(snb[wid] + half * 144);
        d4[j]      = s4[j];
        d4[j + 16] = s4[j + 16];
        if (j < 4) d4[j + 32] = s4[j + 32];
        __syncwarp();
        const int* my = snb[wid] + half * 144 + j * 9;

        int r[K_], c[K_];
        int rmin = 32, cmin = 32, rmax = -1, cmax = -1;
        #pragma unroll
        for (int k = 0; k < K_; k++) {
            int v = my[k];
            r[k] = v >> 5; c[k] = v & 31;
            rmin = min(rmin, r[k]);  rmax = max(rmax, r[k]);
            cmin = min(cmin, c[k]);  cmax = max(cmax, c[k]);
        }
        #pragma unroll
        for (int o = 16; o; o >>= 1) {
            rmin = min(rmin, __shfl_xor_sync(0xffffffffu, rmin, o));
            rmax = max(rmax, __shfl_xor_sync(0xffffffffu, rmax, o));
            cmin = min(cmin, __shfl_xor_sync(0xffffffffu, cmin, o));
            cmax = max(cmax, __shfl_xor_sync(0xffffffffu, cmax, o));
        }
        const int rspan = rmax - rmin, cspan = cmax - cmin;
        int mode;
        if (rspan <= 3 && cspan <= 7)      mode = 0;
        else if (rspan <= 4 && cspan <= 5) mode = 1;
        else                               mode = 2;

        unsigned long long pk = 0;
        if (mode < 2) {
            #pragma unroll
            for (int k = 0; k < K_; k++) {
                int dr = r[k] - rmin, dc = c[k] - cmin;
                unsigned long long sl =
                    (unsigned long long)(mode == 0 ? dr * 8 + dc : dr * 6 + dc);
                pk |= sl << (5 * k);
            }
        }
        g_pack[p] = pk;
        if (lane == 0)
            g_wbase[W] = (unsigned)(mode | (rmin << 2) | (cmin << 7));
    } else {
        const int w = (cta - 64) * 8 + (tid >> 5);
        if (w < NC_) {
            int base = 0;
            #pragma unroll
            for (int chunk = 0; chunk < BS_ / 32; chunk++) {
                int i = chunk * 32 + lane;
                int v = cls_ids[i];
                unsigned m = __ballot_sync(0xffffffffu, v == w);
                if (v == w)
                    g_off[w][base + __popc(m & ((1u << lane) - 1))] =
                        make_int2(i * (NF_ * P_LO_), i * (NF_ * P_HI_));
                base += __popc(m);
            }
            if (lane == 0) g_cls_count[w] = base;
        }
    }
}

// Warp-autonomous main kernel (R13 skeleton): one CTA per (tile, f, c).
// Serial prologue chain is only: hot g_wbase load -> sidx -> x load; the fat
// g_pack and 9 streaming weight loads are independent and overlap it.
__global__ void __launch_bounds__(256, 5)
upsample_kernel(const float* __restrict__ x,
                const int*   __restrict__ nbr,
                const float* __restrict__ wmap,
                const float* __restrict__ blo,
                const float* __restrict__ bhi,
                float*       __restrict__ out)
{
    const int f = blockIdx.y;
    const int c = blockIdx.z;
    const int n = g_cls_count[c];
    if (n == 0) return;

    const int tid  = threadIdx.x;
    const int lane = tid & 31;
    const int wid  = tid >> 5;
    const int W = blockIdx.x * 8 + wid;
    const int h = W >> 3, t = W & 7;
    const int row = 2 * h + (lane >> 4);
    const int col = 16 * t + (lane & 15);
    const int p = row * 128 + col;

    const unsigned wb = g_wbase[W];              // tiny + hot: fast
    const unsigned long long pk = g_pack[p];     // in flight, needed later

    // streaming weights (read-once): 9 independent LDG.cs
    const float* wp = wmap + (((size_t)c * NF_ + f) * P_HI_ + (size_t)p) * K_;
    float wv[K_];
    #pragma unroll
    for (int k = 0; k < K_; k++) wv[k] = __ldcs(wp + k);

    const float bh = bhi[((size_t)c * NF_ + f) * P_HI_ + p];

    const float* blo_cf = blo + ((size_t)c * NF_ + f) * P_LO_;
    const float* x_f    = x   + (size_t)f * P_LO_;
    float*       o_f    = out + (size_t)f * P_HI_ + p;

    const int mode = (int)(wb & 3);

    if (mode < 2) {
        const int r0 = (int)((wb >> 2) & 31);
        const int c0 = (int)((wb >> 7) & 31);
        const int srow = min(r0 + (mode == 0 ? (lane >> 3) : lane / 6), 31);
        const int scol = min(c0 + (mode == 0 ? (lane & 7)  : lane % 6), 31);
        const int sidx = srow * 32 + scol;

        const float  blo_s = blo_cf[sidx];
        const float* xbase = x_f + sidx;

        int sl[K_];
        #pragma unroll
        for (int k = 0; k < K_; k++) sl[k] = (int)((pk >> (5 * k)) & 31);

        // 3-deep rolling sample prefetch
        int2  o0 = g_off[c][0];
        int2  o1 = (n > 1) ? g_off[c][1] : o0;
        int2  o2 = (n > 2) ? g_off[c][2] : o0;
        float v0 = xbase[o0.x];
        float v1 = xbase[o1.x];
        float v2 = xbase[o2.x];

        for (int s = 0; s < n; s++) {
            const float y  = v0 - blo_s;
            const int   oo = o0.y;
            o0 = o1; v0 = v1;
            o1 = o2; v1 = v2;
            if (s + 3 < n) {
                o2 = g_off[c][s + 3];
                v2 = xbase[o2.x];
            }
            float acc = bh;
            #pragma unroll
            for (int k = 0; k < K_; k++)
                acc = fmaf(wv[k], __shfl_sync(0xffffffffu, y, sl[k]), acc);
            __stcs(o_f + oo, acc);
        }
    } else {
        // Safety net: direct global gather (cold path).
        int nb[K_];
        float blo_nb[K_];
        #pragma unroll
        for (int k = 0; k < K_; k++) {
            nb[k]     = nbr[p * K_ + k];
            blo_nb[k] = blo_cf[nb[k]];
        }
        for (int s = 0; s < n; s++) {
            const int2 of = g_off[c][s];
            const float* xs = x_f + of.x;
            float acc = bh;
            #pragma unroll
            for (int k = 0; k < K_; k++)
                acc = fmaf(wv[k], xs[nb[k]] - blo_nb[k], acc);
            __stcs(o_f + of.y, acc);
        }
    }
}

extern "C" void kernel_launch(void* const* d_in, const int* in_sizes, int n_in,
                              void* d_out, int out_size) {
    const float* x    = (const float*)d_in[0];   // (BS, NF*P_LO) f32
    const int*   cls  = (const int*)  d_in[1];   // (BS,) i32
    const int*   nbr  = (const int*)  d_in[2];   // (P_HI, K) i32
    const float* wmap = (const float*)d_in[3];   // (NC, NF, P_HI, K) f32
    const float* blo  = (const float*)d_in[4];   // (NC, NF, P_LO) f32
    const float* bhi  = (const float*)d_in[5];   // (NC, NF, P_HI) f32
    float* out = (float*)d_out;                  // (BS, NF, P_HI) f32

    prepass_kernel<<<69, 256>>>(cls, nbr);
    dim3 grid(64, NF_, NC_);
    upsample_kernel<<<grid, 256>>>(x, nbr, wmap, blo, bhi, out);
}